// round 14
// baseline (speedup 1.0000x reference)
#include <cuda_runtime.h>
#include <cuda_fp16.h>
#include <cstdint>
#include <cstddef>

#define Bb   16
#define Cc   128
#define Hh   64
#define Ww   64
#define NHh  8
#define HDd  16
#define HW   4096
#define OUTC 512

// ---------------------------------------------------------------------------
// Scratch
// ---------------------------------------------------------------------------
__device__ __half g_s[Bb * Cc * HW];          // CPE out, half
__device__ __half g_srch[Bb * Cc * HW];       // src, half
__device__ __half g_qkv[Bb * 3 * Cc * HW];    // qkv, half
__device__ float  g_lambda[Bb * NHh * HDd * HDd];
__device__ float  g_poolpart[Bb * Cc * 4];    // per-quarter partial sums
__device__ __half g_w2b[Bb * OUTC * Cc];      // half, lda=128
__device__ __half g_r1[Bb * Cc * HW];         // half
__device__ __half g_wq[3 * Cc * Cc];          // qkv_w half, lda=128
__device__ __half g_w1[OUTC * Cc];            // out_w[:, :128] half, lda=128

// ---------------------------------------------------------------------------
// helpers
// ---------------------------------------------------------------------------
__device__ __forceinline__ void mma_f16(float* c, const uint32_t* a, const uint32_t* b) {
    asm volatile(
        "mma.sync.aligned.m16n8k16.row.col.f32.f16.f16.f32 "
        "{%0,%1,%2,%3}, {%4,%5,%6,%7}, {%8,%9}, {%0,%1,%2,%3};\n"
        : "+f"(c[0]), "+f"(c[1]), "+f"(c[2]), "+f"(c[3])
        : "r"(a[0]), "r"(a[1]), "r"(a[2]), "r"(a[3]), "r"(b[0]), "r"(b[1]));
}

__device__ __forceinline__ void ldsm_x4(uint32_t* r, uint32_t addr) {
    asm volatile("ldmatrix.sync.aligned.m8n8.x4.shared.b16 {%0,%1,%2,%3}, [%4];"
                 : "=r"(r[0]), "=r"(r[1]), "=r"(r[2]), "=r"(r[3]) : "r"(addr));
}
__device__ __forceinline__ void ldsm_x2t(uint32_t* r, uint32_t addr) {
    asm volatile("ldmatrix.sync.aligned.m8n8.x2.trans.shared.b16 {%0,%1}, [%2];"
                 : "=r"(r[0]), "=r"(r[1]) : "r"(addr));
}

__device__ __forceinline__ void cp16(uint32_t smem, const void* gptr) {
    asm volatile("cp.async.cg.shared.global [%0], [%1], 16;\n" :: "r"(smem), "l"(gptr));
}
__device__ __forceinline__ void cp_commit() {
    asm volatile("cp.async.commit_group;\n");
}
template <int N>
__device__ __forceinline__ void cp_wait() {
    asm volatile("cp.async.wait_group %0;\n" :: "n"(N));
}

__device__ __forceinline__ void store2(__half* p, float a, float b) {
    *reinterpret_cast<__half2*>(p) = __floats2half2_rn(a, b);
}
__device__ __forceinline__ void store2(float* p, float a, float b) {
    *reinterpret_cast<float2*>(p) = make_float2(a, b);
}

// ---------------------------------------------------------------------------
// 1) CPE (half out) + src half copy + pool quarter-partials (exact R13)
// ---------------------------------------------------------------------------
__global__ __launch_bounds__(256) void k_cpe(const float* __restrict__ src,
                                             const float* __restrict__ cpe_w,
                                             __half* __restrict__ s,
                                             __half* __restrict__ srch,
                                             float* __restrict__ poolpart) {
    int gid = blockIdx.x * 256 + threadIdx.x;
    int p4 = gid * 4;
    int x = p4 & 63;
    int h = (p4 >> 6) & 63;
    int c = (p4 >> 12) & 127;
    const float* wp = cpe_w + c * 9;

    float a0 = 0.f, a1 = 0.f, a2 = 0.f, a3 = 0.f;
    float4 ctr = *reinterpret_cast<const float4*>(src + p4);

#pragma unroll
    for (int dy = -1; dy <= 1; dy++) {
        int hy = h + dy;
        if (hy < 0 || hy >= Hh) continue;
        const float* r = src + p4 + dy * Ww;
        float4 m = (dy == 0) ? ctr : *reinterpret_cast<const float4*>(r);
        float lft = (x > 0)  ? r[-1] : 0.f;
        float rgt = (x < 60) ? r[4]  : 0.f;
        float wl = wp[(dy + 1) * 3 + 0];
        float wc = wp[(dy + 1) * 3 + 1];
        float wr = wp[(dy + 1) * 3 + 2];
        a0 += wl * lft + wc * m.x + wr * m.y;
        a1 += wl * m.x + wc * m.y + wr * m.z;
        a2 += wl * m.y + wc * m.z + wr * m.w;
        a3 += wl * m.z + wc * m.w + wr * rgt;
    }
    __half2* sp = reinterpret_cast<__half2*>(s + p4);
    sp[0] = __floats2half2_rn(a0 + ctr.x, a1 + ctr.y);
    sp[1] = __floats2half2_rn(a2 + ctr.z, a3 + ctr.w);
    __half2* cph = reinterpret_cast<__half2*>(srch + p4);
    cph[0] = __floats2half2_rn(ctr.x, ctr.y);
    cph[1] = __floats2half2_rn(ctr.z, ctr.w);

    float psum = ctr.x + ctr.y + ctr.z + ctr.w;
    __shared__ float sm[256];
    sm[threadIdx.x] = psum;
    __syncthreads();
    for (int sstep = 128; sstep > 0; sstep >>= 1) {
        if (threadIdx.x < sstep) sm[threadIdx.x] += sm[threadIdx.x + sstep];
        __syncthreads();
    }
    if (threadIdx.x == 0) poolpart[blockIdx.x] = sm[0];
}

// ---------------------------------------------------------------------------
// 2) fused wconv + ECA + w2b (exact R13)
// ---------------------------------------------------------------------------
__device__ __forceinline__ float poolsum(const float* pp, int pc) {
    return pp[pc * 4] + pp[pc * 4 + 1] + pp[pc * 4 + 2] + pp[pc * 4 + 3];
}

__global__ __launch_bounds__(256) void k_w2b(const float* __restrict__ qkv_w,
                                             const float* __restrict__ out_w,
                                             const float* __restrict__ poolpart,
                                             const float* __restrict__ conv1d_w,
                                             __half* __restrict__ wq,
                                             __half* __restrict__ w1,
                                             __half* __restrict__ w2b) {
    int idx = blockIdx.x * 256 + threadIdx.x;
    if (idx >= Bb * OUTC * Cc) return;
    if (idx < 3 * Cc * Cc) wq[idx] = __float2half_rn(qkv_w[idx]);
    if (idx < OUTC * Cc) {
        int o = idx >> 7, c2 = idx & 127;
        w1[idx] = __float2half_rn(out_w[o * 256 + c2]);
    }
    int c = idx & 127;
    int o = (idx >> 7) & 511;
    int b = idx >> 16;
    int pc = (b << 7) + c;
    const float inv = 1.0f / HW;
    float left  = (c > 0)   ? poolsum(poolpart, pc - 1) * inv : 0.f;
    float mid   = poolsum(poolpart, pc) * inv;
    float right = (c < 127) ? poolsum(poolpart, pc + 1) * inv : 0.f;
    float z = conv1d_w[0] * left + conv1d_w[1] * mid + conv1d_w[2] * right;
    float ca = 1.0f / (1.0f + __expf(-z));
    w2b[idx] = __float2half_rn(out_w[o * 256 + 128 + c] * ca);
}

// ---------------------------------------------------------------------------
// 3) fp16 GEMM (exact R13)
// ---------------------------------------------------------------------------
template <int NPARTS, typename OutT>
__global__ __launch_bounds__(256, 2) void k_mma_gemm(
    const __half* __restrict__ A0, size_t sA0,
    const __half* __restrict__ B0, size_t sB0,
    const __half* __restrict__ A1, size_t sA1,
    const __half* __restrict__ B1, size_t sB1,
    OutT* __restrict__ C, size_t sC) {
    constexpr int BlkM = 128, BlkN = 128, BlkK = 16;
    constexpr int ASTh = 24;
    constexpr int BSTh = 136;
    constexpr int ASZh = BlkM * ASTh;
    constexpr int BSZh = BlkK * BSTh;

    extern __shared__ __half smh[];
    __half* Asm = smh;
    __half* Bsm = smh + 3 * ASZh;
    const uint32_t a_base0 = (uint32_t)__cvta_generic_to_shared(Asm);
    const uint32_t b_base0 = (uint32_t)__cvta_generic_to_shared(Bsm);

    const int tid = threadIdx.x;
    const int bz = blockIdx.z, mtile = blockIdx.x, ntile = blockIdx.y;
    const int warp = tid >> 5, lane = tid & 31;
    const int g = lane >> 2, t = lane & 3;
    const int wm = (warp >> 2) * 64;
    const int wn = (warp & 3) * 32;

    auto load_chunk = [&](int cidx, int buf) {
        const int part = (NPARTS == 2) ? (cidx >> 3) : 0;
        const int kin = (cidx & 7) * BlkK;
        const __half* Aptr = part ? A1 + (size_t)bz * sA1 : A0 + (size_t)bz * sA0;
        const __half* Bptr = part ? B1 + (size_t)bz * sB1 : B0 + (size_t)bz * sB0;
        __half* Abuf = Asm + buf * ASZh;
        __half* Bbuf = Bsm + buf * BSZh;
        {
            int row = tid >> 1, ho = (tid & 1) * 8;
            cp16((uint32_t)__cvta_generic_to_shared(&Abuf[row * ASTh + ho]),
                 Aptr + (size_t)(mtile * BlkM + row) * 128 + kin + ho);
        }
        {
            int kk = tid >> 4, col = (tid & 15) * 8;
            cp16((uint32_t)__cvta_generic_to_shared(&Bbuf[kk * BSTh + col]),
                 Bptr + (size_t)(kin + kk) * HW + ntile * BlkN + col);
        }
        cp_commit();
    };

    float acc[4][4][4];
#pragma unroll
    for (int f = 0; f < 4; f++)
#pragma unroll
        for (int nf = 0; nf < 4; nf++)
#pragma unroll
            for (int j = 0; j < 4; j++) acc[f][nf][j] = 0.f;

    const int a_row_in = (lane & 7) + ((lane >> 3) & 1) * 8;
    const int a_kbase  = (lane >> 4) * 8;
    const int b_krow   = lane & 15;

    auto compute = [&](int buf) {
        const uint32_t a_base = a_base0 + buf * ASZh * 2;
        const uint32_t b_base = b_base0 + buf * BSZh * 2;
        uint32_t areg[4][4];
#pragma unroll
        for (int f = 0; f < 4; f++) {
            uint32_t addr = a_base +
                (uint32_t)(((wm + f * 16 + a_row_in) * ASTh + a_kbase) * 2);
            ldsm_x4(areg[f], addr);
        }
        uint32_t breg[4][2];
#pragma unroll
        for (int nf = 0; nf < 4; nf++) {
            uint32_t addr = b_base +
                (uint32_t)((b_krow * BSTh + wn + nf * 8) * 2);
            ldsm_x2t(breg[nf], addr);
        }
#pragma unroll
        for (int f = 0; f < 4; f++)
#pragma unroll
            for (int nf = 0; nf < 4; nf++)
                mma_f16(acc[f][nf], areg[f], breg[nf]);
    };

    const int NC = NPARTS * 8;
    load_chunk(0, 0);
    load_chunk(1, 1);
    for (int cidx = 0; cidx < NC; cidx++) {
        if (cidx < NC - 1) cp_wait<1>(); else cp_wait<0>();
        __syncthreads();
        if (cidx + 2 < NC) load_chunk(cidx + 2, (cidx + 2) % 3);
        compute(cidx % 3);
    }

    OutT* Cbase = C + (size_t)bz * sC + (size_t)(mtile * BlkM) * HW + ntile * BlkN;
#pragma unroll
    for (int f = 0; f < 4; f++) {
#pragma unroll
        for (int nf = 0; nf < 4; nf++) {
            int row = wm + f * 16 + g;
            int col = wn + nf * 8 + t * 2;
            store2(Cbase + (size_t)row * HW + col, acc[f][nf][0], acc[f][nf][1]);
            store2(Cbase + (size_t)(row + 8) * HW + col, acc[f][nf][2], acc[f][nf][3]);
        }
    }
}

// ---------------------------------------------------------------------------
// 4) softmax + lambda. grid (bh=128, quad=4), block 128.
//    Each block: COMPLETE lambda rows for 4 k-rows {4p..4p+3} over all n.
//    v staged per 512-chunk as fp32 (cvts amortized); inner loop float4,
//    one slot per thread per chunk. Writes normalized g_lambda.
// ---------------------------------------------------------------------------
__global__ __launch_bounds__(128) void k_softmax_lambda(const __half* __restrict__ qkv,
                                                        float* __restrict__ lambda) {
    const int bh = blockIdx.x;
    const int quad = blockIdx.y;
    const int i0 = quad * 4;
    const int b = bh >> 3, nh = bh & 7;
    const __half* kbase = qkv + ((size_t)b * 384 + 128 + nh * 16) * HW;
    const __half* vbase = qkv + ((size_t)b * 384 + 256 + nh * 16) * HW;
    const int tid = threadIdx.x;
    const int warp = tid >> 5, lane = tid & 31;

    __shared__ float vsm[16][512];     // 32 KB
    __shared__ float red[4][4][17];    // [warp][row][o|se]

    float acc[4][16];
#pragma unroll
    for (int r = 0; r < 4; r++)
#pragma unroll
        for (int o = 0; o < 16; o++) acc[r][o] = 0.f;
    float se[4] = {0.f, 0.f, 0.f, 0.f};

    const int n_slot = tid * 4;   // this thread's float4 slot within each chunk

    for (int n0 = 0; n0 < HW; n0 += 512) {
        __syncthreads();
        // stage v chunk, converting half2 -> float once
        for (int t2 = tid; t2 < 16 * 256; t2 += 128) {
            int o = t2 >> 8, n2 = t2 & 255;
            __half2 hv = *reinterpret_cast<const __half2*>(
                vbase + (size_t)o * HW + n0 + n2 * 2);
            vsm[o][n2 * 2]     = __low2float(hv);
            vsm[o][n2 * 2 + 1] = __high2float(hv);
        }
        __syncthreads();

        // k values for this thread's 4-n slot, all 4 rows
        float e[4][4];
#pragma unroll
        for (int r = 0; r < 4; r++) {
            uint2 kr = *reinterpret_cast<const uint2*>(
                kbase + (size_t)(i0 + r) * HW + n0 + n_slot);
            __half2 ha = *reinterpret_cast<__half2*>(&kr.x);
            __half2 hb = *reinterpret_cast<__half2*>(&kr.y);
            e[r][0] = __expf(__low2float(ha));
            e[r][1] = __expf(__high2float(ha));
            e[r][2] = __expf(__low2float(hb));
            e[r][3] = __expf(__high2float(hb));
            se[r] += e[r][0] + e[r][1] + e[r][2] + e[r][3];
        }
#pragma unroll
        for (int o = 0; o < 16; o++) {
            float4 v = *reinterpret_cast<const float4*>(&vsm[o][n_slot]);
#pragma unroll
            for (int r = 0; r < 4; r++) {
                acc[r][o] += e[r][0] * v.x + e[r][1] * v.y
                           + e[r][2] * v.z + e[r][3] * v.w;
            }
        }
    }

    // warp-level reduction
#pragma unroll
    for (int off = 16; off > 0; off >>= 1) {
#pragma unroll
        for (int r = 0; r < 4; r++) {
            se[r] += __shfl_xor_sync(0xffffffff, se[r], off);
#pragma unroll
            for (int o = 0; o < 16; o++)
                acc[r][o] += __shfl_xor_sync(0xffffffff, acc[r][o], off);
        }
    }
    if (lane < 16) {
#pragma unroll
        for (int r = 0; r < 4; r++) red[warp][r][lane] = acc[r][lane];
    } else if (lane == 16) {
#pragma unroll
        for (int r = 0; r < 4; r++) red[warp][r][16] = se[r];
    }
    __syncthreads();
    if (tid < 64) {
        int r = tid >> 4, o = tid & 15;
        float a = red[0][r][o] + red[1][r][o] + red[2][r][o] + red[3][r][o];
        float s = red[0][r][16] + red[1][r][16] + red[2][r][16] + red[3][r][16];
        lambda[(size_t)bh * 256 + (i0 + r) * 16 + o] = 0.25f * a / s;
    }
}

// ---------------------------------------------------------------------------
// 5) result1 = content + q * position_lambda (exact R13)
// ---------------------------------------------------------------------------
__global__ __launch_bounds__(256) void k_result1(const __half* __restrict__ qkv,
                                                 const float* __restrict__ lambda,
                                                 const float* __restrict__ rel_pos,
                                                 __half* __restrict__ r1) {
    const int bh = blockIdx.z;
    const int b = bh >> 3, nh = bh & 7;
    const int x0 = blockIdx.x * 16, y0 = blockIdx.y * 16;
    const int tid = threadIdx.x;
    const int px = tid & 15, py = tid >> 4;

    __shared__ float lam[16][16];
    __shared__ float relw[16][25];
    __shared__ float qs[16][16][16];
    __shared__ float vs[16][20][20];

    lam[py][px] = lambda[((size_t)bh * 16 + py) * 16 + px];
    for (int t = tid; t < 400; t += 256) relw[t / 25][t % 25] = rel_pos[t];
    const __half* qbase = qkv + ((size_t)b * 384 + nh * 16) * HW;
#pragma unroll
    for (int ch = 0; ch < 16; ch++)
        qs[ch][py][px] = __half2float(qbase[(size_t)ch * HW + (y0 + py) * Ww + x0 + px]);
    const __half* vbase = qkv + ((size_t)b * 384 + 256 + nh * 16) * HW;
    for (int t = tid; t < 6400; t += 256) {
        int ch = t / 400;
        int r = t % 400;
        int vy = r / 20, vx = r % 20;
        int gy = y0 + vy - 2, gx = x0 + vx - 2;
        float val = 0.f;
        if (gy >= 0 && gy < Hh && gx >= 0 && gx < Ww)
            val = __half2float(vbase[(size_t)ch * HW + gy * Ww + gx]);
        vs[ch][vy][vx] = val;
    }
    __syncthreads();

    __half* obase = r1 + ((size_t)b * Cc + nh * 16) * HW + (y0 + py) * Ww + x0 + px;
#pragma unroll
    for (int o = 0; o < 16; o++) {
        float content = 0.f;
#pragma unroll
        for (int i = 0; i < 16; i++) content += qs[i][py][px] * lam[i][o];
        float pos = 0.f;
#pragma unroll
        for (int ky = 0; ky < 5; ky++)
#pragma unroll
            for (int kx = 0; kx < 5; kx++)
                pos += relw[o][ky * 5 + kx] * vs[o][py + ky][px + kx];
        obase[(size_t)o * HW] = __float2half_rn(content + qs[o][py][px] * pos);
    }
}

// ---------------------------------------------------------------------------
// Launch
// ---------------------------------------------------------------------------
extern "C" void kernel_launch(void* const* d_in, const int* in_sizes, int n_in,
                              void* d_out, int out_size) {
    const float* src      = (const float*)d_in[0];
    const float* cpe_w    = (const float*)d_in[1];
    const float* qkv_w    = (const float*)d_in[2];
    const float* rel_pos  = (const float*)d_in[3];
    const float* conv1d_w = (const float*)d_in[4];
    const float* out_w    = (const float*)d_in[5];
    float* out = (float*)d_out;

    __half *s_p, *srch_p, *qkv_p, *w2b_p, *r1_p, *wq_p, *w1_p;
    float *lam_p, *pp_p;
    cudaGetSymbolAddress((void**)&s_p,    g_s);
    cudaGetSymbolAddress((void**)&srch_p, g_srch);
    cudaGetSymbolAddress((void**)&qkv_p,  g_qkv);
    cudaGetSymbolAddress((void**)&lam_p,  g_lambda);
    cudaGetSymbolAddress((void**)&pp_p,   g_poolpart);
    cudaGetSymbolAddress((void**)&w2b_p,  g_w2b);
    cudaGetSymbolAddress((void**)&r1_p,   g_r1);
    cudaGetSymbolAddress((void**)&wq_p,   g_wq);
    cudaGetSymbolAddress((void**)&w1_p,   g_w1);

    const int gemm_smem = 3 * (128 * 24 + 16 * 136) * 2;  // 31488 bytes
    cudaFuncSetAttribute(k_mma_gemm<1, __half>, cudaFuncAttributeMaxDynamicSharedMemorySize, gemm_smem);
    cudaFuncSetAttribute(k_mma_gemm<2, float>,  cudaFuncAttributeMaxDynamicSharedMemorySize, gemm_smem);

    k_cpe<<<Bb * Cc * HW / 1024, 256>>>(src, cpe_w, s_p, srch_p, pp_p);
    k_w2b<<<(Bb * OUTC * Cc + 255) / 256, 256>>>(qkv_w, out_w, pp_p, conv1d_w,
                                                 wq_p, w1_p, w2b_p);
    {
        dim3 grid(3 * Cc / 128, HW / 128, Bb);
        k_mma_gemm<1, __half><<<grid, 256, gemm_smem>>>(wq_p, 0,
                                                        s_p, (size_t)Cc * HW,
                                                        nullptr, 0, nullptr, 0,
                                                        qkv_p, (size_t)3 * Cc * HW);
    }
    {
        dim3 grid(Bb * NHh, 4);
        k_softmax_lambda<<<grid, 128>>>(qkv_p, lam_p);
    }
    {
        dim3 grid(Ww / 16, Hh / 16, Bb * NHh);
        k_result1<<<grid, 256>>>(qkv_p, lam_p, rel_pos, r1_p);
    }
    {
        dim3 grid(OUTC / 128, HW / 128, Bb);
        k_mma_gemm<2, float><<<grid, 256, gemm_smem>>>(w1_p, 0,
                                                       r1_p, (size_t)Cc * HW,
                                                       w2b_p, (size_t)OUTC * Cc,
                                                       srch_p, (size_t)Cc * HW,
                                                       out, (size_t)OUTC * HW);
    }
}

// round 15
// speedup vs baseline: 1.0043x; 1.0043x over previous
#include <cuda_runtime.h>
#include <cuda_fp16.h>
#include <cstdint>
#include <cstddef>

#define Bb   16
#define Cc   128
#define Hh   64
#define Ww   64
#define NHh  8
#define HDd  16
#define HW   4096
#define OUTC 512

// ---------------------------------------------------------------------------
// Scratch
// ---------------------------------------------------------------------------
__device__ __half g_s[Bb * Cc * HW];          // CPE out, half
__device__ __half g_srch[Bb * Cc * HW];       // src, half
__device__ __half g_qkv[Bb * 3 * Cc * HW];    // qkv, half
__device__ float  g_lambda[Bb * NHh * HDd * HDd];
__device__ float  g_poolpart[Bb * Cc * 4];    // per-quarter partial sums
__device__ __half g_w2b[Bb * OUTC * Cc];      // half, lda=128
__device__ __half g_r1[Bb * Cc * HW];         // half
__device__ __half g_wq[3 * Cc * Cc];          // qkv_w half, lda=128
__device__ __half g_w1[OUTC * Cc];            // out_w[:, :128] half, lda=128

// ---------------------------------------------------------------------------
// helpers
// ---------------------------------------------------------------------------
__device__ __forceinline__ void mma_f16(float* c, const uint32_t* a, const uint32_t* b) {
    asm volatile(
        "mma.sync.aligned.m16n8k16.row.col.f32.f16.f16.f32 "
        "{%0,%1,%2,%3}, {%4,%5,%6,%7}, {%8,%9}, {%0,%1,%2,%3};\n"
        : "+f"(c[0]), "+f"(c[1]), "+f"(c[2]), "+f"(c[3])
        : "r"(a[0]), "r"(a[1]), "r"(a[2]), "r"(a[3]), "r"(b[0]), "r"(b[1]));
}

__device__ __forceinline__ void ldsm_x4(uint32_t* r, uint32_t addr) {
    asm volatile("ldmatrix.sync.aligned.m8n8.x4.shared.b16 {%0,%1,%2,%3}, [%4];"
                 : "=r"(r[0]), "=r"(r[1]), "=r"(r[2]), "=r"(r[3]) : "r"(addr));
}
__device__ __forceinline__ void ldsm_x2t(uint32_t* r, uint32_t addr) {
    asm volatile("ldmatrix.sync.aligned.m8n8.x2.trans.shared.b16 {%0,%1}, [%2];"
                 : "=r"(r[0]), "=r"(r[1]) : "r"(addr));
}

__device__ __forceinline__ void cp16(uint32_t smem, const void* gptr) {
    asm volatile("cp.async.cg.shared.global [%0], [%1], 16;\n" :: "r"(smem), "l"(gptr));
}
__device__ __forceinline__ void cp_commit() {
    asm volatile("cp.async.commit_group;\n");
}
template <int N>
__device__ __forceinline__ void cp_wait() {
    asm volatile("cp.async.wait_group %0;\n" :: "n"(N));
}

__device__ __forceinline__ void store2(__half* p, float a, float b) {
    *reinterpret_cast<__half2*>(p) = __floats2half2_rn(a, b);
}
__device__ __forceinline__ void store2(float* p, float a, float b) {
    *reinterpret_cast<float2*>(p) = make_float2(a, b);
}

// ---------------------------------------------------------------------------
// 1) CPE (half out) + src half copy + pool quarter-partials (exact R13)
// ---------------------------------------------------------------------------
__global__ __launch_bounds__(256) void k_cpe(const float* __restrict__ src,
                                             const float* __restrict__ cpe_w,
                                             __half* __restrict__ s,
                                             __half* __restrict__ srch,
                                             float* __restrict__ poolpart) {
    int gid = blockIdx.x * 256 + threadIdx.x;
    int p4 = gid * 4;
    int x = p4 & 63;
    int h = (p4 >> 6) & 63;
    int c = (p4 >> 12) & 127;
    const float* wp = cpe_w + c * 9;

    float a0 = 0.f, a1 = 0.f, a2 = 0.f, a3 = 0.f;
    float4 ctr = *reinterpret_cast<const float4*>(src + p4);

#pragma unroll
    for (int dy = -1; dy <= 1; dy++) {
        int hy = h + dy;
        if (hy < 0 || hy >= Hh) continue;
        const float* r = src + p4 + dy * Ww;
        float4 m = (dy == 0) ? ctr : *reinterpret_cast<const float4*>(r);
        float lft = (x > 0)  ? r[-1] : 0.f;
        float rgt = (x < 60) ? r[4]  : 0.f;
        float wl = wp[(dy + 1) * 3 + 0];
        float wc = wp[(dy + 1) * 3 + 1];
        float wr = wp[(dy + 1) * 3 + 2];
        a0 += wl * lft + wc * m.x + wr * m.y;
        a1 += wl * m.x + wc * m.y + wr * m.z;
        a2 += wl * m.y + wc * m.z + wr * m.w;
        a3 += wl * m.z + wc * m.w + wr * rgt;
    }
    __half2* sp = reinterpret_cast<__half2*>(s + p4);
    sp[0] = __floats2half2_rn(a0 + ctr.x, a1 + ctr.y);
    sp[1] = __floats2half2_rn(a2 + ctr.z, a3 + ctr.w);
    __half2* cph = reinterpret_cast<__half2*>(srch + p4);
    cph[0] = __floats2half2_rn(ctr.x, ctr.y);
    cph[1] = __floats2half2_rn(ctr.z, ctr.w);

    float psum = ctr.x + ctr.y + ctr.z + ctr.w;
    __shared__ float sm[256];
    sm[threadIdx.x] = psum;
    __syncthreads();
    for (int sstep = 128; sstep > 0; sstep >>= 1) {
        if (threadIdx.x < sstep) sm[threadIdx.x] += sm[threadIdx.x + sstep];
        __syncthreads();
    }
    if (threadIdx.x == 0) poolpart[blockIdx.x] = sm[0];
}

// ---------------------------------------------------------------------------
// 2) fused wconv + ECA + w2b (exact R13)
// ---------------------------------------------------------------------------
__device__ __forceinline__ float poolsum(const float* pp, int pc) {
    return pp[pc * 4] + pp[pc * 4 + 1] + pp[pc * 4 + 2] + pp[pc * 4 + 3];
}

__global__ __launch_bounds__(256) void k_w2b(const float* __restrict__ qkv_w,
                                             const float* __restrict__ out_w,
                                             const float* __restrict__ poolpart,
                                             const float* __restrict__ conv1d_w,
                                             __half* __restrict__ wq,
                                             __half* __restrict__ w1,
                                             __half* __restrict__ w2b) {
    int idx = blockIdx.x * 256 + threadIdx.x;
    if (idx >= Bb * OUTC * Cc) return;
    if (idx < 3 * Cc * Cc) wq[idx] = __float2half_rn(qkv_w[idx]);
    if (idx < OUTC * Cc) {
        int o = idx >> 7, c2 = idx & 127;
        w1[idx] = __float2half_rn(out_w[o * 256 + c2]);
    }
    int c = idx & 127;
    int o = (idx >> 7) & 511;
    int b = idx >> 16;
    int pc = (b << 7) + c;
    const float inv = 1.0f / HW;
    float left  = (c > 0)   ? poolsum(poolpart, pc - 1) * inv : 0.f;
    float mid   = poolsum(poolpart, pc) * inv;
    float right = (c < 127) ? poolsum(poolpart, pc + 1) * inv : 0.f;
    float z = conv1d_w[0] * left + conv1d_w[1] * mid + conv1d_w[2] * right;
    float ca = 1.0f / (1.0f + __expf(-z));
    w2b[idx] = __float2half_rn(out_w[o * 256 + 128 + c] * ca);
}

// ---------------------------------------------------------------------------
// 3) fp16 GEMM (exact R13)
// ---------------------------------------------------------------------------
template <int NPARTS, typename OutT>
__global__ __launch_bounds__(256, 2) void k_mma_gemm(
    const __half* __restrict__ A0, size_t sA0,
    const __half* __restrict__ B0, size_t sB0,
    const __half* __restrict__ A1, size_t sA1,
    const __half* __restrict__ B1, size_t sB1,
    OutT* __restrict__ C, size_t sC) {
    constexpr int BlkM = 128, BlkN = 128, BlkK = 16;
    constexpr int ASTh = 24;
    constexpr int BSTh = 136;
    constexpr int ASZh = BlkM * ASTh;
    constexpr int BSZh = BlkK * BSTh;

    extern __shared__ __half smh[];
    __half* Asm = smh;
    __half* Bsm = smh + 3 * ASZh;
    const uint32_t a_base0 = (uint32_t)__cvta_generic_to_shared(Asm);
    const uint32_t b_base0 = (uint32_t)__cvta_generic_to_shared(Bsm);

    const int tid = threadIdx.x;
    const int bz = blockIdx.z, mtile = blockIdx.x, ntile = blockIdx.y;
    const int warp = tid >> 5, lane = tid & 31;
    const int g = lane >> 2, t = lane & 3;
    const int wm = (warp >> 2) * 64;
    const int wn = (warp & 3) * 32;

    auto load_chunk = [&](int cidx, int buf) {
        const int part = (NPARTS == 2) ? (cidx >> 3) : 0;
        const int kin = (cidx & 7) * BlkK;
        const __half* Aptr = part ? A1 + (size_t)bz * sA1 : A0 + (size_t)bz * sA0;
        const __half* Bptr = part ? B1 + (size_t)bz * sB1 : B0 + (size_t)bz * sB0;
        __half* Abuf = Asm + buf * ASZh;
        __half* Bbuf = Bsm + buf * BSZh;
        {
            int row = tid >> 1, ho = (tid & 1) * 8;
            cp16((uint32_t)__cvta_generic_to_shared(&Abuf[row * ASTh + ho]),
                 Aptr + (size_t)(mtile * BlkM + row) * 128 + kin + ho);
        }
        {
            int kk = tid >> 4, col = (tid & 15) * 8;
            cp16((uint32_t)__cvta_generic_to_shared(&Bbuf[kk * BSTh + col]),
                 Bptr + (size_t)(kin + kk) * HW + ntile * BlkN + col);
        }
        cp_commit();
    };

    float acc[4][4][4];
#pragma unroll
    for (int f = 0; f < 4; f++)
#pragma unroll
        for (int nf = 0; nf < 4; nf++)
#pragma unroll
            for (int j = 0; j < 4; j++) acc[f][nf][j] = 0.f;

    const int a_row_in = (lane & 7) + ((lane >> 3) & 1) * 8;
    const int a_kbase  = (lane >> 4) * 8;
    const int b_krow   = lane & 15;

    auto compute = [&](int buf) {
        const uint32_t a_base = a_base0 + buf * ASZh * 2;
        const uint32_t b_base = b_base0 + buf * BSZh * 2;
        uint32_t areg[4][4];
#pragma unroll
        for (int f = 0; f < 4; f++) {
            uint32_t addr = a_base +
                (uint32_t)(((wm + f * 16 + a_row_in) * ASTh + a_kbase) * 2);
            ldsm_x4(areg[f], addr);
        }
        uint32_t breg[4][2];
#pragma unroll
        for (int nf = 0; nf < 4; nf++) {
            uint32_t addr = b_base +
                (uint32_t)((b_krow * BSTh + wn + nf * 8) * 2);
            ldsm_x2t(breg[nf], addr);
        }
#pragma unroll
        for (int f = 0; f < 4; f++)
#pragma unroll
            for (int nf = 0; nf < 4; nf++)
                mma_f16(acc[f][nf], areg[f], breg[nf]);
    };

    const int NC = NPARTS * 8;
    load_chunk(0, 0);
    load_chunk(1, 1);
    for (int cidx = 0; cidx < NC; cidx++) {
        if (cidx < NC - 1) cp_wait<1>(); else cp_wait<0>();
        __syncthreads();
        if (cidx + 2 < NC) load_chunk(cidx + 2, (cidx + 2) % 3);
        compute(cidx % 3);
    }

    OutT* Cbase = C + (size_t)bz * sC + (size_t)(mtile * BlkM) * HW + ntile * BlkN;
#pragma unroll
    for (int f = 0; f < 4; f++) {
#pragma unroll
        for (int nf = 0; nf < 4; nf++) {
            int row = wm + f * 16 + g;
            int col = wn + nf * 8 + t * 2;
            store2(Cbase + (size_t)row * HW + col, acc[f][nf][0], acc[f][nf][1]);
            store2(Cbase + (size_t)(row + 8) * HW + col, acc[f][nf][2], acc[f][nf][3]);
        }
    }
}

// ---------------------------------------------------------------------------
// 4) softmax + lambda. grid (bh=128, pair=8), block 256 (8 warps).
//    2 k-rows per block (32 acc regs); v staged per 512-chunk as fp32
//    (cvt once at staging); inner loop: one float2 slot per thread.
// ---------------------------------------------------------------------------
__global__ __launch_bounds__(256) void k_softmax_lambda(const __half* __restrict__ qkv,
                                                        float* __restrict__ lambda) {
    const int bh = blockIdx.x;
    const int pair = blockIdx.y;
    const int i0 = pair * 2;
    const int b = bh >> 3, nh = bh & 7;
    const __half* kbase = qkv + ((size_t)b * 384 + 128 + nh * 16) * HW;
    const __half* vbase = qkv + ((size_t)b * 384 + 256 + nh * 16) * HW;
    const int tid = threadIdx.x;
    const int warp = tid >> 5, lane = tid & 31;

    __shared__ float vsm[16][512];     // 32 KB
    __shared__ float red[8][2][17];    // [warp][row][o|se]

    const __half* k0 = kbase + (size_t)(i0 + 0) * HW;
    const __half* k1 = kbase + (size_t)(i0 + 1) * HW;

    float acc0[16], acc1[16];
#pragma unroll
    for (int o = 0; o < 16; o++) { acc0[o] = 0.f; acc1[o] = 0.f; }
    float se0 = 0.f, se1 = 0.f;

    const int n2s = tid * 2;   // this thread's float2 slot (n offset)

    for (int n0 = 0; n0 < HW; n0 += 512) {
        __syncthreads();
        // stage v chunk as fp32 (cvt once)
        for (int t2 = tid; t2 < 16 * 256; t2 += 256) {
            int o = t2 >> 8, n2 = t2 & 255;
            __half2 hv = *reinterpret_cast<const __half2*>(
                vbase + (size_t)o * HW + n0 + n2 * 2);
            vsm[o][n2 * 2]     = __low2float(hv);
            vsm[o][n2 * 2 + 1] = __high2float(hv);
        }
        __syncthreads();

        __half2 kk0 = *reinterpret_cast<const __half2*>(k0 + n0 + n2s);
        __half2 kk1 = *reinterpret_cast<const __half2*>(k1 + n0 + n2s);
        float e00 = __expf(__low2float(kk0)), e01 = __expf(__high2float(kk0));
        float e10 = __expf(__low2float(kk1)), e11 = __expf(__high2float(kk1));
        se0 += e00 + e01;
        se1 += e10 + e11;
#pragma unroll
        for (int o = 0; o < 16; o++) {
            float2 v = *reinterpret_cast<const float2*>(&vsm[o][n2s]);
            acc0[o] += e00 * v.x + e01 * v.y;
            acc1[o] += e10 * v.x + e11 * v.y;
        }
    }

    // warp-level reduction
#pragma unroll
    for (int off = 16; off > 0; off >>= 1) {
        se0 += __shfl_xor_sync(0xffffffff, se0, off);
        se1 += __shfl_xor_sync(0xffffffff, se1, off);
#pragma unroll
        for (int o = 0; o < 16; o++) {
            acc0[o] += __shfl_xor_sync(0xffffffff, acc0[o], off);
            acc1[o] += __shfl_xor_sync(0xffffffff, acc1[o], off);
        }
    }
    if (lane < 16) {
        red[warp][0][lane] = acc0[lane];
        red[warp][1][lane] = acc1[lane];
    } else if (lane == 16) {
        red[warp][0][16] = se0;
        red[warp][1][16] = se1;
    }
    __syncthreads();
    if (tid < 32) {
        int r = tid >> 4, o = tid & 15;
        float a = 0.f, s = 0.f;
#pragma unroll
        for (int w = 0; w < 8; w++) {
            a += red[w][r][o];
            s += red[w][r][16];
        }
        lambda[(size_t)bh * 256 + (i0 + r) * 16 + o] = 0.25f * a / s;
    }
}

// ---------------------------------------------------------------------------
// 5) result1 = content + q * position_lambda (exact R13)
// ---------------------------------------------------------------------------
__global__ __launch_bounds__(256) void k_result1(const __half* __restrict__ qkv,
                                                 const float* __restrict__ lambda,
                                                 const float* __restrict__ rel_pos,
                                                 __half* __restrict__ r1) {
    const int bh = blockIdx.z;
    const int b = bh >> 3, nh = bh & 7;
    const int x0 = blockIdx.x * 16, y0 = blockIdx.y * 16;
    const int tid = threadIdx.x;
    const int px = tid & 15, py = tid >> 4;

    __shared__ float lam[16][16];
    __shared__ float relw[16][25];
    __shared__ float qs[16][16][16];
    __shared__ float vs[16][20][20];

    lam[py][px] = lambda[((size_t)bh * 16 + py) * 16 + px];
    for (int t = tid; t < 400; t += 256) relw[t / 25][t % 25] = rel_pos[t];
    const __half* qbase = qkv + ((size_t)b * 384 + nh * 16) * HW;
#pragma unroll
    for (int ch = 0; ch < 16; ch++)
        qs[ch][py][px] = __half2float(qbase[(size_t)ch * HW + (y0 + py) * Ww + x0 + px]);
    const __half* vbase = qkv + ((size_t)b * 384 + 256 + nh * 16) * HW;
    for (int t = tid; t < 6400; t += 256) {
        int ch = t / 400;
        int r = t % 400;
        int vy = r / 20, vx = r % 20;
        int gy = y0 + vy - 2, gx = x0 + vx - 2;
        float val = 0.f;
        if (gy >= 0 && gy < Hh && gx >= 0 && gx < Ww)
            val = __half2float(vbase[(size_t)ch * HW + gy * Ww + gx]);
        vs[ch][vy][vx] = val;
    }
    __syncthreads();

    __half* obase = r1 + ((size_t)b * Cc + nh * 16) * HW + (y0 + py) * Ww + x0 + px;
#pragma unroll
    for (int o = 0; o < 16; o++) {
        float content = 0.f;
#pragma unroll
        for (int i = 0; i < 16; i++) content += qs[i][py][px] * lam[i][o];
        float pos = 0.f;
#pragma unroll
        for (int ky = 0; ky < 5; ky++)
#pragma unroll
            for (int kx = 0; kx < 5; kx++)
                pos += relw[o][ky * 5 + kx] * vs[o][py + ky][px + kx];
        obase[(size_t)o * HW] = __float2half_rn(content + qs[o][py][px] * pos);
    }
}

// ---------------------------------------------------------------------------
// Launch
// ---------------------------------------------------------------------------
extern "C" void kernel_launch(void* const* d_in, const int* in_sizes, int n_in,
                              void* d_out, int out_size) {
    const float* src      = (const float*)d_in[0];
    const float* cpe_w    = (const float*)d_in[1];
    const float* qkv_w    = (const float*)d_in[2];
    const float* rel_pos  = (const float*)d_in[3];
    const float* conv1d_w = (const float*)d_in[4];
    const float* out_w    = (const float*)d_in[5];
    float* out = (float*)d_out;

    __half *s_p, *srch_p, *qkv_p, *w2b_p, *r1_p, *wq_p, *w1_p;
    float *lam_p, *pp_p;
    cudaGetSymbolAddress((void**)&s_p,    g_s);
    cudaGetSymbolAddress((void**)&srch_p, g_srch);
    cudaGetSymbolAddress((void**)&qkv_p,  g_qkv);
    cudaGetSymbolAddress((void**)&lam_p,  g_lambda);
    cudaGetSymbolAddress((void**)&pp_p,   g_poolpart);
    cudaGetSymbolAddress((void**)&w2b_p,  g_w2b);
    cudaGetSymbolAddress((void**)&r1_p,   g_r1);
    cudaGetSymbolAddress((void**)&wq_p,   g_wq);
    cudaGetSymbolAddress((void**)&w1_p,   g_w1);

    const int gemm_smem = 3 * (128 * 24 + 16 * 136) * 2;  // 31488 bytes
    cudaFuncSetAttribute(k_mma_gemm<1, __half>, cudaFuncAttributeMaxDynamicSharedMemorySize, gemm_smem);
    cudaFuncSetAttribute(k_mma_gemm<2, float>,  cudaFuncAttributeMaxDynamicSharedMemorySize, gemm_smem);

    k_cpe<<<Bb * Cc * HW / 1024, 256>>>(src, cpe_w, s_p, srch_p, pp_p);
    k_w2b<<<(Bb * OUTC * Cc + 255) / 256, 256>>>(qkv_w, out_w, pp_p, conv1d_w,
                                                 wq_p, w1_p, w2b_p);
    {
        dim3 grid(3 * Cc / 128, HW / 128, Bb);
        k_mma_gemm<1, __half><<<grid, 256, gemm_smem>>>(wq_p, 0,
                                                        s_p, (size_t)Cc * HW,
                                                        nullptr, 0, nullptr, 0,
                                                        qkv_p, (size_t)3 * Cc * HW);
    }
    {
        dim3 grid(Bb * NHh, 8);
        k_softmax_lambda<<<grid, 256>>>(qkv_p, lam_p);
    }
    {
        dim3 grid(Ww / 16, Hh / 16, Bb * NHh);
        k_result1<<<grid, 256>>>(qkv_p, lam_p, rel_pos, r1_p);
    }
    {
        dim3 grid(OUTC / 128, HW / 128, Bb);
        k_mma_gemm<2, float><<<grid, 256, gemm_smem>>>(w1_p, 0,
                                                       r1_p, (size_t)Cc * HW,
                                                       w2b_p, (size_t)OUTC * Cc,
                                                       srch_p, (size_t)Cc * HW,
                                                       out, (size_t)OUTC * HW);
    }
}

// round 16
// speedup vs baseline: 1.0937x; 1.0891x over previous
#include <cuda_runtime.h>
#include <cuda_fp16.h>
#include <cstdint>
#include <cstddef>

#define Bb   16
#define Cc   128
#define Hh   64
#define Ww   64
#define NHh  8
#define HDd  16
#define HW   4096
#define OUTC 512

// ---------------------------------------------------------------------------
// Scratch
// ---------------------------------------------------------------------------
__device__ __half g_s[Bb * Cc * HW];          // CPE out, half
__device__ __half g_srch[Bb * Cc * HW];       // src, half
__device__ __half g_qkv[Bb * 3 * Cc * HW];    // qkv, half
__device__ float  g_lambda[Bb * NHh * HDd * HDd];
__device__ float  g_poolpart[Bb * Cc * 4];    // per-quarter partial sums
__device__ __half g_w2b[Bb * OUTC * Cc];      // half, lda=128
__device__ __half g_r1[Bb * Cc * HW];         // half
__device__ __half g_wq[3 * Cc * Cc];          // qkv_w half, lda=128
__device__ __half g_w1[OUTC * Cc];            // out_w[:, :128] half, lda=128

// ---------------------------------------------------------------------------
// helpers
// ---------------------------------------------------------------------------
__device__ __forceinline__ void mma_f16(float* c, const uint32_t* a, const uint32_t* b) {
    asm volatile(
        "mma.sync.aligned.m16n8k16.row.col.f32.f16.f16.f32 "
        "{%0,%1,%2,%3}, {%4,%5,%6,%7}, {%8,%9}, {%0,%1,%2,%3};\n"
        : "+f"(c[0]), "+f"(c[1]), "+f"(c[2]), "+f"(c[3])
        : "r"(a[0]), "r"(a[1]), "r"(a[2]), "r"(a[3]), "r"(b[0]), "r"(b[1]));
}

__device__ __forceinline__ void ldsm_x4(uint32_t* r, uint32_t addr) {
    asm volatile("ldmatrix.sync.aligned.m8n8.x4.shared.b16 {%0,%1,%2,%3}, [%4];"
                 : "=r"(r[0]), "=r"(r[1]), "=r"(r[2]), "=r"(r[3]) : "r"(addr));
}
__device__ __forceinline__ void ldsm_x2t(uint32_t* r, uint32_t addr) {
    asm volatile("ldmatrix.sync.aligned.m8n8.x2.trans.shared.b16 {%0,%1}, [%2];"
                 : "=r"(r[0]), "=r"(r[1]) : "r"(addr));
}

__device__ __forceinline__ void cp16(uint32_t smem, const void* gptr) {
    asm volatile("cp.async.cg.shared.global [%0], [%1], 16;\n" :: "r"(smem), "l"(gptr));
}
__device__ __forceinline__ void cp_commit() {
    asm volatile("cp.async.commit_group;\n");
}
template <int N>
__device__ __forceinline__ void cp_wait() {
    asm volatile("cp.async.wait_group %0;\n" :: "n"(N));
}

__device__ __forceinline__ void store2(__half* p, float a, float b) {
    *reinterpret_cast<__half2*>(p) = __floats2half2_rn(a, b);
}
__device__ __forceinline__ void store2(float* p, float a, float b) {
    *reinterpret_cast<float2*>(p) = make_float2(a, b);
}

// ---------------------------------------------------------------------------
// 1) CPE (half out) + src half copy + pool quarter-partials (exact R13)
// ---------------------------------------------------------------------------
__global__ __launch_bounds__(256) void k_cpe(const float* __restrict__ src,
                                             const float* __restrict__ cpe_w,
                                             __half* __restrict__ s,
                                             __half* __restrict__ srch,
                                             float* __restrict__ poolpart) {
    int gid = blockIdx.x * 256 + threadIdx.x;
    int p4 = gid * 4;
    int x = p4 & 63;
    int h = (p4 >> 6) & 63;
    int c = (p4 >> 12) & 127;
    const float* wp = cpe_w + c * 9;

    float a0 = 0.f, a1 = 0.f, a2 = 0.f, a3 = 0.f;
    float4 ctr = *reinterpret_cast<const float4*>(src + p4);

#pragma unroll
    for (int dy = -1; dy <= 1; dy++) {
        int hy = h + dy;
        if (hy < 0 || hy >= Hh) continue;
        const float* r = src + p4 + dy * Ww;
        float4 m = (dy == 0) ? ctr : *reinterpret_cast<const float4*>(r);
        float lft = (x > 0)  ? r[-1] : 0.f;
        float rgt = (x < 60) ? r[4]  : 0.f;
        float wl = wp[(dy + 1) * 3 + 0];
        float wc = wp[(dy + 1) * 3 + 1];
        float wr = wp[(dy + 1) * 3 + 2];
        a0 += wl * lft + wc * m.x + wr * m.y;
        a1 += wl * m.x + wc * m.y + wr * m.z;
        a2 += wl * m.y + wc * m.z + wr * m.w;
        a3 += wl * m.z + wc * m.w + wr * rgt;
    }
    __half2* sp = reinterpret_cast<__half2*>(s + p4);
    sp[0] = __floats2half2_rn(a0 + ctr.x, a1 + ctr.y);
    sp[1] = __floats2half2_rn(a2 + ctr.z, a3 + ctr.w);
    __half2* cph = reinterpret_cast<__half2*>(srch + p4);
    cph[0] = __floats2half2_rn(ctr.x, ctr.y);
    cph[1] = __floats2half2_rn(ctr.z, ctr.w);

    float psum = ctr.x + ctr.y + ctr.z + ctr.w;
    __shared__ float sm[256];
    sm[threadIdx.x] = psum;
    __syncthreads();
    for (int sstep = 128; sstep > 0; sstep >>= 1) {
        if (threadIdx.x < sstep) sm[threadIdx.x] += sm[threadIdx.x + sstep];
        __syncthreads();
    }
    if (threadIdx.x == 0) poolpart[blockIdx.x] = sm[0];
}

// ---------------------------------------------------------------------------
// 2) fused wconv + ECA + w2b (exact R13)
// ---------------------------------------------------------------------------
__device__ __forceinline__ float poolsum(const float* pp, int pc) {
    return pp[pc * 4] + pp[pc * 4 + 1] + pp[pc * 4 + 2] + pp[pc * 4 + 3];
}

__global__ __launch_bounds__(256) void k_w2b(const float* __restrict__ qkv_w,
                                             const float* __restrict__ out_w,
                                             const float* __restrict__ poolpart,
                                             const float* __restrict__ conv1d_w,
                                             __half* __restrict__ wq,
                                             __half* __restrict__ w1,
                                             __half* __restrict__ w2b) {
    int idx = blockIdx.x * 256 + threadIdx.x;
    if (idx >= Bb * OUTC * Cc) return;
    if (idx < 3 * Cc * Cc) wq[idx] = __float2half_rn(qkv_w[idx]);
    if (idx < OUTC * Cc) {
        int o = idx >> 7, c2 = idx & 127;
        w1[idx] = __float2half_rn(out_w[o * 256 + c2]);
    }
    int c = idx & 127;
    int o = (idx >> 7) & 511;
    int b = idx >> 16;
    int pc = (b << 7) + c;
    const float inv = 1.0f / HW;
    float left  = (c > 0)   ? poolsum(poolpart, pc - 1) * inv : 0.f;
    float mid   = poolsum(poolpart, pc) * inv;
    float right = (c < 127) ? poolsum(poolpart, pc + 1) * inv : 0.f;
    float z = conv1d_w[0] * left + conv1d_w[1] * mid + conv1d_w[2] * right;
    float ca = 1.0f / (1.0f + __expf(-z));
    w2b[idx] = __float2half_rn(out_w[o * 256 + 128 + c] * ca);
}

// ---------------------------------------------------------------------------
// 3) fp16 GEMM (exact R13)
// ---------------------------------------------------------------------------
template <int NPARTS, typename OutT>
__global__ __launch_bounds__(256, 2) void k_mma_gemm(
    const __half* __restrict__ A0, size_t sA0,
    const __half* __restrict__ B0, size_t sB0,
    const __half* __restrict__ A1, size_t sA1,
    const __half* __restrict__ B1, size_t sB1,
    OutT* __restrict__ C, size_t sC) {
    constexpr int BlkM = 128, BlkN = 128, BlkK = 16;
    constexpr int ASTh = 24;
    constexpr int BSTh = 136;
    constexpr int ASZh = BlkM * ASTh;
    constexpr int BSZh = BlkK * BSTh;

    extern __shared__ __half smh[];
    __half* Asm = smh;
    __half* Bsm = smh + 3 * ASZh;
    const uint32_t a_base0 = (uint32_t)__cvta_generic_to_shared(Asm);
    const uint32_t b_base0 = (uint32_t)__cvta_generic_to_shared(Bsm);

    const int tid = threadIdx.x;
    const int bz = blockIdx.z, mtile = blockIdx.x, ntile = blockIdx.y;
    const int warp = tid >> 5, lane = tid & 31;
    const int g = lane >> 2, t = lane & 3;
    const int wm = (warp >> 2) * 64;
    const int wn = (warp & 3) * 32;

    auto load_chunk = [&](int cidx, int buf) {
        const int part = (NPARTS == 2) ? (cidx >> 3) : 0;
        const int kin = (cidx & 7) * BlkK;
        const __half* Aptr = part ? A1 + (size_t)bz * sA1 : A0 + (size_t)bz * sA0;
        const __half* Bptr = part ? B1 + (size_t)bz * sB1 : B0 + (size_t)bz * sB0;
        __half* Abuf = Asm + buf * ASZh;
        __half* Bbuf = Bsm + buf * BSZh;
        {
            int row = tid >> 1, ho = (tid & 1) * 8;
            cp16((uint32_t)__cvta_generic_to_shared(&Abuf[row * ASTh + ho]),
                 Aptr + (size_t)(mtile * BlkM + row) * 128 + kin + ho);
        }
        {
            int kk = tid >> 4, col = (tid & 15) * 8;
            cp16((uint32_t)__cvta_generic_to_shared(&Bbuf[kk * BSTh + col]),
                 Bptr + (size_t)(kin + kk) * HW + ntile * BlkN + col);
        }
        cp_commit();
    };

    float acc[4][4][4];
#pragma unroll
    for (int f = 0; f < 4; f++)
#pragma unroll
        for (int nf = 0; nf < 4; nf++)
#pragma unroll
            for (int j = 0; j < 4; j++) acc[f][nf][j] = 0.f;

    const int a_row_in = (lane & 7) + ((lane >> 3) & 1) * 8;
    const int a_kbase  = (lane >> 4) * 8;
    const int b_krow   = lane & 15;

    auto compute = [&](int buf) {
        const uint32_t a_base = a_base0 + buf * ASZh * 2;
        const uint32_t b_base = b_base0 + buf * BSZh * 2;
        uint32_t areg[4][4];
#pragma unroll
        for (int f = 0; f < 4; f++) {
            uint32_t addr = a_base +
                (uint32_t)(((wm + f * 16 + a_row_in) * ASTh + a_kbase) * 2);
            ldsm_x4(areg[f], addr);
        }
        uint32_t breg[4][2];
#pragma unroll
        for (int nf = 0; nf < 4; nf++) {
            uint32_t addr = b_base +
                (uint32_t)((b_krow * BSTh + wn + nf * 8) * 2);
            ldsm_x2t(breg[nf], addr);
        }
#pragma unroll
        for (int f = 0; f < 4; f++)
#pragma unroll
            for (int nf = 0; nf < 4; nf++)
                mma_f16(acc[f][nf], areg[f], breg[nf]);
    };

    const int NC = NPARTS * 8;
    load_chunk(0, 0);
    load_chunk(1, 1);
    for (int cidx = 0; cidx < NC; cidx++) {
        if (cidx < NC - 1) cp_wait<1>(); else cp_wait<0>();
        __syncthreads();
        if (cidx + 2 < NC) load_chunk(cidx + 2, (cidx + 2) % 3);
        compute(cidx % 3);
    }

    OutT* Cbase = C + (size_t)bz * sC + (size_t)(mtile * BlkM) * HW + ntile * BlkN;
#pragma unroll
    for (int f = 0; f < 4; f++) {
#pragma unroll
        for (int nf = 0; nf < 4; nf++) {
            int row = wm + f * 16 + g;
            int col = wn + nf * 8 + t * 2;
            store2(Cbase + (size_t)row * HW + col, acc[f][nf][0], acc[f][nf][1]);
            store2(Cbase + (size_t)(row + 8) * HW + col, acc[f][nf][2], acc[f][nf][3]);
        }
    }
}

// ---------------------------------------------------------------------------
// 4) softmax + lambda (R13 structure + cp.async double-buffered v staging).
//    grid (bh=128, pair=8), block 128 (4 warps), 2 k-rows per block.
// ---------------------------------------------------------------------------
__global__ __launch_bounds__(128) void k_softmax_lambda(const __half* __restrict__ qkv,
                                                        float* __restrict__ lambda) {
    const int bh = blockIdx.x;
    const int pair = blockIdx.y;
    const int i0 = pair * 2;
    const int b = bh >> 3, nh = bh & 7;
    const __half* kbase = qkv + ((size_t)b * 384 + 128 + nh * 16) * HW;
    const __half* vbase = qkv + ((size_t)b * 384 + 256 + nh * 16) * HW;
    const int tid = threadIdx.x;
    const int warp = tid >> 5, lane = tid & 31;

    __shared__ __half2 vsm[2][16][256];   // 2 x 16 KB
    __shared__ float red[4][2][17];

    const uint32_t vsm_base = (uint32_t)__cvta_generic_to_shared(&vsm[0][0][0]);

    const __half* k0 = kbase + (size_t)(i0 + 0) * HW;
    const __half* k1 = kbase + (size_t)(i0 + 1) * HW;

    // prefetch chunk: 16 rows x 1024B = 1024 cp16; 8 per thread
    auto prefetch = [&](int n0, int buf) {
#pragma unroll
        for (int i = 0; i < 8; i++) {
            int t2 = tid + i * 128;          // 0..1023
            int o = t2 >> 6, grp = t2 & 63;  // row, 16B group
            cp16(vsm_base + (uint32_t)(buf * 16384 + o * 1024 + grp * 16),
                 vbase + (size_t)o * HW + n0 + grp * 8);
        }
        cp_commit();
    };

    float acc0[16], acc1[16];
#pragma unroll
    for (int o = 0; o < 16; o++) { acc0[o] = 0.f; acc1[o] = 0.f; }
    float se0 = 0.f, se1 = 0.f;

    prefetch(0, 0);
    for (int c = 0; c < 8; c++) {
        const int n0 = c * 512;
        cp_wait<0>();
        __syncthreads();             // chunk c ready; compute(c-1) fully done
        if (c + 1 < 8) prefetch((c + 1) * 512, (c + 1) & 1);
        const int buf = c & 1;
        // warps partition the 256 half2 slots: warp w -> [w*64, w*64+64)
#pragma unroll
        for (int it = 0; it < 2; it++) {
            int n2 = warp * 64 + it * 32 + lane;
            __half2 kk0 = *reinterpret_cast<const __half2*>(k0 + n0 + n2 * 2);
            __half2 kk1 = *reinterpret_cast<const __half2*>(k1 + n0 + n2 * 2);
            float e00 = __expf(__low2float(kk0)), e01 = __expf(__high2float(kk0));
            float e10 = __expf(__low2float(kk1)), e11 = __expf(__high2float(kk1));
            se0 += e00 + e01;
            se1 += e10 + e11;
#pragma unroll
            for (int o = 0; o < 16; o++) {
                __half2 hv = vsm[buf][o][n2];
                float vx = __low2float(hv), vy = __high2float(hv);
                acc0[o] += e00 * vx + e01 * vy;
                acc1[o] += e10 * vx + e11 * vy;
            }
        }
    }

    // warp-level reduction
#pragma unroll
    for (int off = 16; off > 0; off >>= 1) {
        se0 += __shfl_xor_sync(0xffffffff, se0, off);
        se1 += __shfl_xor_sync(0xffffffff, se1, off);
#pragma unroll
        for (int o = 0; o < 16; o++) {
            acc0[o] += __shfl_xor_sync(0xffffffff, acc0[o], off);
            acc1[o] += __shfl_xor_sync(0xffffffff, acc1[o], off);
        }
    }
    if (lane < 16) {
        red[warp][0][lane] = acc0[lane];
        red[warp][1][lane] = acc1[lane];
    } else if (lane == 16) {
        red[warp][0][16] = se0;
        red[warp][1][16] = se1;
    }
    __syncthreads();
    if (tid < 32) {
        int r = tid >> 4, o = tid & 15;
        float a = red[0][r][o] + red[1][r][o] + red[2][r][o] + red[3][r][o];
        float s = red[0][r][16] + red[1][r][16] + red[2][r][16] + red[3][r][16];
        lambda[(size_t)bh * 256 + (i0 + r) * 16 + o] = 0.25f * a / s;
    }
}

// ---------------------------------------------------------------------------
// 5) result1 = content + q * position_lambda (exact R13)
// ---------------------------------------------------------------------------
__global__ __launch_bounds__(256) void k_result1(const __half* __restrict__ qkv,
                                                 const float* __restrict__ lambda,
                                                 const float* __restrict__ rel_pos,
                                                 __half* __restrict__ r1) {
    const int bh = blockIdx.z;
    const int b = bh >> 3, nh = bh & 7;
    const int x0 = blockIdx.x * 16, y0 = blockIdx.y * 16;
    const int tid = threadIdx.x;
    const int px = tid & 15, py = tid >> 4;

    __shared__ float lam[16][16];
    __shared__ float relw[16][25];
    __shared__ float qs[16][16][16];
    __shared__ float vs[16][20][20];

    lam[py][px] = lambda[((size_t)bh * 16 + py) * 16 + px];
    for (int t = tid; t < 400; t += 256) relw[t / 25][t % 25] = rel_pos[t];
    const __half* qbase = qkv + ((size_t)b * 384 + nh * 16) * HW;
#pragma unroll
    for (int ch = 0; ch < 16; ch++)
        qs[ch][py][px] = __half2float(qbase[(size_t)ch * HW + (y0 + py) * Ww + x0 + px]);
    const __half* vbase = qkv + ((size_t)b * 384 + 256 + nh * 16) * HW;
    for (int t = tid; t < 6400; t += 256) {
        int ch = t / 400;
        int r = t % 400;
        int vy = r / 20, vx = r % 20;
        int gy = y0 + vy - 2, gx = x0 + vx - 2;
        float val = 0.f;
        if (gy >= 0 && gy < Hh && gx >= 0 && gx < Ww)
            val = __half2float(vbase[(size_t)ch * HW + gy * Ww + gx]);
        vs[ch][vy][vx] = val;
    }
    __syncthreads();

    __half* obase = r1 + ((size_t)b * Cc + nh * 16) * HW + (y0 + py) * Ww + x0 + px;
#pragma unroll
    for (int o = 0; o < 16; o++) {
        float content = 0.f;
#pragma unroll
        for (int i = 0; i < 16; i++) content += qs[i][py][px] * lam[i][o];
        float pos = 0.f;
#pragma unroll
        for (int ky = 0; ky < 5; ky++)
#pragma unroll
            for (int kx = 0; kx < 5; kx++)
                pos += relw[o][ky * 5 + kx] * vs[o][py + ky][px + kx];
        obase[(size_t)o * HW] = __float2half_rn(content + qs[o][py][px] * pos);
    }
}

// ---------------------------------------------------------------------------
// Launch
// ---------------------------------------------------------------------------
extern "C" void kernel_launch(void* const* d_in, const int* in_sizes, int n_in,
                              void* d_out, int out_size) {
    const float* src      = (const float*)d_in[0];
    const float* cpe_w    = (const float*)d_in[1];
    const float* qkv_w    = (const float*)d_in[2];
    const float* rel_pos  = (const float*)d_in[3];
    const float* conv1d_w = (const float*)d_in[4];
    const float* out_w    = (const float*)d_in[5];
    float* out = (float*)d_out;

    __half *s_p, *srch_p, *qkv_p, *w2b_p, *r1_p, *wq_p, *w1_p;
    float *lam_p, *pp_p;
    cudaGetSymbolAddress((void**)&s_p,    g_s);
    cudaGetSymbolAddress((void**)&srch_p, g_srch);
    cudaGetSymbolAddress((void**)&qkv_p,  g_qkv);
    cudaGetSymbolAddress((void**)&lam_p,  g_lambda);
    cudaGetSymbolAddress((void**)&pp_p,   g_poolpart);
    cudaGetSymbolAddress((void**)&w2b_p,  g_w2b);
    cudaGetSymbolAddress((void**)&r1_p,   g_r1);
    cudaGetSymbolAddress((void**)&wq_p,   g_wq);
    cudaGetSymbolAddress((void**)&w1_p,   g_w1);

    const int gemm_smem = 3 * (128 * 24 + 16 * 136) * 2;  // 31488 bytes
    cudaFuncSetAttribute(k_mma_gemm<1, __half>, cudaFuncAttributeMaxDynamicSharedMemorySize, gemm_smem);
    cudaFuncSetAttribute(k_mma_gemm<2, float>,  cudaFuncAttributeMaxDynamicSharedMemorySize, gemm_smem);

    k_cpe<<<Bb * Cc * HW / 1024, 256>>>(src, cpe_w, s_p, srch_p, pp_p);
    k_w2b<<<(Bb * OUTC * Cc + 255) / 256, 256>>>(qkv_w, out_w, pp_p, conv1d_w,
                                                 wq_p, w1_p, w2b_p);
    {
        dim3 grid(3 * Cc / 128, HW / 128, Bb);
        k_mma_gemm<1, __half><<<grid, 256, gemm_smem>>>(wq_p, 0,
                                                        s_p, (size_t)Cc * HW,
                                                        nullptr, 0, nullptr, 0,
                                                        qkv_p, (size_t)3 * Cc * HW);
    }
    {
        dim3 grid(Bb * NHh, 8);
        k_softmax_lambda<<<grid, 128>>>(qkv_p, lam_p);
    }
    {
        dim3 grid(Ww / 16, Hh / 16, Bb * NHh);
        k_result1<<<grid, 256>>>(qkv_p, lam_p, rel_pos, r1_p);
    }
    {
        dim3 grid(OUTC / 128, HW / 128, Bb);
        k_mma_gemm<2, float><<<grid, 256, gemm_smem>>>(w1_p, 0,
                                                       r1_p, (size_t)Cc * HW,
                                                       w2b_p, (size_t)OUTC * Cc,
                                                       srch_p, (size_t)Cc * HW,
                                                       out, (size_t)OUTC * HW);
    }
}

// round 17
// speedup vs baseline: 1.0939x; 1.0001x over previous
#include <cuda_runtime.h>
#include <cuda_fp16.h>
#include <cstdint>
#include <cstddef>

#define Bb   16
#define Cc   128
#define Hh   64
#define Ww   64
#define NHh  8
#define HDd  16
#define HW   4096
#define OUTC 512

// ---------------------------------------------------------------------------
// Scratch
// ---------------------------------------------------------------------------
__device__ __half g_s[Bb * Cc * HW];          // CPE out, half
__device__ __half g_srch[Bb * Cc * HW];       // src, half
__device__ __half g_qkv[Bb * 3 * Cc * HW];    // qkv, half
__device__ float  g_lambda[Bb * NHh * HDd * HDd];
__device__ float  g_poolpart[Bb * Cc * 4];    // per-quarter partial sums
__device__ __half g_w2b[Bb * OUTC * Cc];      // half, lda=128
__device__ __half g_r1[Bb * Cc * HW];         // half
__device__ __half g_wq[3 * Cc * Cc];          // qkv_w half, lda=128
__device__ __half g_w1[OUTC * Cc];            // out_w[:, :128] half, lda=128

// ---------------------------------------------------------------------------
// helpers
// ---------------------------------------------------------------------------
__device__ __forceinline__ void mma_f16(float* c, const uint32_t* a, const uint32_t* b) {
    asm volatile(
        "mma.sync.aligned.m16n8k16.row.col.f32.f16.f16.f32 "
        "{%0,%1,%2,%3}, {%4,%5,%6,%7}, {%8,%9}, {%0,%1,%2,%3};\n"
        : "+f"(c[0]), "+f"(c[1]), "+f"(c[2]), "+f"(c[3])
        : "r"(a[0]), "r"(a[1]), "r"(a[2]), "r"(a[3]), "r"(b[0]), "r"(b[1]));
}

__device__ __forceinline__ void ldsm_x4(uint32_t* r, uint32_t addr) {
    asm volatile("ldmatrix.sync.aligned.m8n8.x4.shared.b16 {%0,%1,%2,%3}, [%4];"
                 : "=r"(r[0]), "=r"(r[1]), "=r"(r[2]), "=r"(r[3]) : "r"(addr));
}
__device__ __forceinline__ void ldsm_x2t(uint32_t* r, uint32_t addr) {
    asm volatile("ldmatrix.sync.aligned.m8n8.x2.trans.shared.b16 {%0,%1}, [%2];"
                 : "=r"(r[0]), "=r"(r[1]) : "r"(addr));
}

__device__ __forceinline__ void cp16(uint32_t smem, const void* gptr) {
    asm volatile("cp.async.cg.shared.global [%0], [%1], 16;\n" :: "r"(smem), "l"(gptr));
}
__device__ __forceinline__ void cp_commit() {
    asm volatile("cp.async.commit_group;\n");
}
template <int N>
__device__ __forceinline__ void cp_wait() {
    asm volatile("cp.async.wait_group %0;\n" :: "n"(N));
}

__device__ __forceinline__ void store2(__half* p, float a, float b) {
    *reinterpret_cast<__half2*>(p) = __floats2half2_rn(a, b);
}
__device__ __forceinline__ void store2(float* p, float a, float b) {
    *reinterpret_cast<float2*>(p) = make_float2(a, b);
}

// ---------------------------------------------------------------------------
// 1) CPE (half out) + src half copy + pool quarter-partials (exact R16)
// ---------------------------------------------------------------------------
__global__ __launch_bounds__(256) void k_cpe(const float* __restrict__ src,
                                             const float* __restrict__ cpe_w,
                                             __half* __restrict__ s,
                                             __half* __restrict__ srch,
                                             float* __restrict__ poolpart) {
    int gid = blockIdx.x * 256 + threadIdx.x;
    int p4 = gid * 4;
    int x = p4 & 63;
    int h = (p4 >> 6) & 63;
    int c = (p4 >> 12) & 127;
    const float* wp = cpe_w + c * 9;

    float a0 = 0.f, a1 = 0.f, a2 = 0.f, a3 = 0.f;
    float4 ctr = *reinterpret_cast<const float4*>(src + p4);

#pragma unroll
    for (int dy = -1; dy <= 1; dy++) {
        int hy = h + dy;
        if (hy < 0 || hy >= Hh) continue;
        const float* r = src + p4 + dy * Ww;
        float4 m = (dy == 0) ? ctr : *reinterpret_cast<const float4*>(r);
        float lft = (x > 0)  ? r[-1] : 0.f;
        float rgt = (x < 60) ? r[4]  : 0.f;
        float wl = wp[(dy + 1) * 3 + 0];
        float wc = wp[(dy + 1) * 3 + 1];
        float wr = wp[(dy + 1) * 3 + 2];
        a0 += wl * lft + wc * m.x + wr * m.y;
        a1 += wl * m.x + wc * m.y + wr * m.z;
        a2 += wl * m.y + wc * m.z + wr * m.w;
        a3 += wl * m.z + wc * m.w + wr * rgt;
    }
    __half2* sp = reinterpret_cast<__half2*>(s + p4);
    sp[0] = __floats2half2_rn(a0 + ctr.x, a1 + ctr.y);
    sp[1] = __floats2half2_rn(a2 + ctr.z, a3 + ctr.w);
    __half2* cph = reinterpret_cast<__half2*>(srch + p4);
    cph[0] = __floats2half2_rn(ctr.x, ctr.y);
    cph[1] = __floats2half2_rn(ctr.z, ctr.w);

    float psum = ctr.x + ctr.y + ctr.z + ctr.w;
    __shared__ float sm[256];
    sm[threadIdx.x] = psum;
    __syncthreads();
    for (int sstep = 128; sstep > 0; sstep >>= 1) {
        if (threadIdx.x < sstep) sm[threadIdx.x] += sm[threadIdx.x + sstep];
        __syncthreads();
    }
    if (threadIdx.x == 0) poolpart[blockIdx.x] = sm[0];
}

// ---------------------------------------------------------------------------
// 2) fused wconv + ECA + w2b (exact R16)
// ---------------------------------------------------------------------------
__device__ __forceinline__ float poolsum(const float* pp, int pc) {
    return pp[pc * 4] + pp[pc * 4 + 1] + pp[pc * 4 + 2] + pp[pc * 4 + 3];
}

__global__ __launch_bounds__(256) void k_w2b(const float* __restrict__ qkv_w,
                                             const float* __restrict__ out_w,
                                             const float* __restrict__ poolpart,
                                             const float* __restrict__ conv1d_w,
                                             __half* __restrict__ wq,
                                             __half* __restrict__ w1,
                                             __half* __restrict__ w2b) {
    int idx = blockIdx.x * 256 + threadIdx.x;
    if (idx >= Bb * OUTC * Cc) return;
    if (idx < 3 * Cc * Cc) wq[idx] = __float2half_rn(qkv_w[idx]);
    if (idx < OUTC * Cc) {
        int o = idx >> 7, c2 = idx & 127;
        w1[idx] = __float2half_rn(out_w[o * 256 + c2]);
    }
    int c = idx & 127;
    int o = (idx >> 7) & 511;
    int b = idx >> 16;
    int pc = (b << 7) + c;
    const float inv = 1.0f / HW;
    float left  = (c > 0)   ? poolsum(poolpart, pc - 1) * inv : 0.f;
    float mid   = poolsum(poolpart, pc) * inv;
    float right = (c < 127) ? poolsum(poolpart, pc + 1) * inv : 0.f;
    float z = conv1d_w[0] * left + conv1d_w[1] * mid + conv1d_w[2] * right;
    float ca = 1.0f / (1.0f + __expf(-z));
    w2b[idx] = __float2half_rn(out_w[o * 256 + 128 + c] * ca);
}

// ---------------------------------------------------------------------------
// 3) fp16 GEMM (exact R16)
// ---------------------------------------------------------------------------
template <int NPARTS, typename OutT>
__global__ __launch_bounds__(256, 2) void k_mma_gemm(
    const __half* __restrict__ A0, size_t sA0,
    const __half* __restrict__ B0, size_t sB0,
    const __half* __restrict__ A1, size_t sA1,
    const __half* __restrict__ B1, size_t sB1,
    OutT* __restrict__ C, size_t sC) {
    constexpr int BlkM = 128, BlkN = 128, BlkK = 16;
    constexpr int ASTh = 24;
    constexpr int BSTh = 136;
    constexpr int ASZh = BlkM * ASTh;
    constexpr int BSZh = BlkK * BSTh;

    extern __shared__ __half smh[];
    __half* Asm = smh;
    __half* Bsm = smh + 3 * ASZh;
    const uint32_t a_base0 = (uint32_t)__cvta_generic_to_shared(Asm);
    const uint32_t b_base0 = (uint32_t)__cvta_generic_to_shared(Bsm);

    const int tid = threadIdx.x;
    const int bz = blockIdx.z, mtile = blockIdx.x, ntile = blockIdx.y;
    const int warp = tid >> 5, lane = tid & 31;
    const int g = lane >> 2, t = lane & 3;
    const int wm = (warp >> 2) * 64;
    const int wn = (warp & 3) * 32;

    auto load_chunk = [&](int cidx, int buf) {
        const int part = (NPARTS == 2) ? (cidx >> 3) : 0;
        const int kin = (cidx & 7) * BlkK;
        const __half* Aptr = part ? A1 + (size_t)bz * sA1 : A0 + (size_t)bz * sA0;
        const __half* Bptr = part ? B1 + (size_t)bz * sB1 : B0 + (size_t)bz * sB0;
        __half* Abuf = Asm + buf * ASZh;
        __half* Bbuf = Bsm + buf * BSZh;
        {
            int row = tid >> 1, ho = (tid & 1) * 8;
            cp16((uint32_t)__cvta_generic_to_shared(&Abuf[row * ASTh + ho]),
                 Aptr + (size_t)(mtile * BlkM + row) * 128 + kin + ho);
        }
        {
            int kk = tid >> 4, col = (tid & 15) * 8;
            cp16((uint32_t)__cvta_generic_to_shared(&Bbuf[kk * BSTh + col]),
                 Bptr + (size_t)(kin + kk) * HW + ntile * BlkN + col);
        }
        cp_commit();
    };

    float acc[4][4][4];
#pragma unroll
    for (int f = 0; f < 4; f++)
#pragma unroll
        for (int nf = 0; nf < 4; nf++)
#pragma unroll
            for (int j = 0; j < 4; j++) acc[f][nf][j] = 0.f;

    const int a_row_in = (lane & 7) + ((lane >> 3) & 1) * 8;
    const int a_kbase  = (lane >> 4) * 8;
    const int b_krow   = lane & 15;

    auto compute = [&](int buf) {
        const uint32_t a_base = a_base0 + buf * ASZh * 2;
        const uint32_t b_base = b_base0 + buf * BSZh * 2;
        uint32_t areg[4][4];
#pragma unroll
        for (int f = 0; f < 4; f++) {
            uint32_t addr = a_base +
                (uint32_t)(((wm + f * 16 + a_row_in) * ASTh + a_kbase) * 2);
            ldsm_x4(areg[f], addr);
        }
        uint32_t breg[4][2];
#pragma unroll
        for (int nf = 0; nf < 4; nf++) {
            uint32_t addr = b_base +
                (uint32_t)((b_krow * BSTh + wn + nf * 8) * 2);
            ldsm_x2t(breg[nf], addr);
        }
#pragma unroll
        for (int f = 0; f < 4; f++)
#pragma unroll
            for (int nf = 0; nf < 4; nf++)
                mma_f16(acc[f][nf], areg[f], breg[nf]);
    };

    const int NC = NPARTS * 8;
    load_chunk(0, 0);
    load_chunk(1, 1);
    for (int cidx = 0; cidx < NC; cidx++) {
        if (cidx < NC - 1) cp_wait<1>(); else cp_wait<0>();
        __syncthreads();
        if (cidx + 2 < NC) load_chunk(cidx + 2, (cidx + 2) % 3);
        compute(cidx % 3);
    }

    OutT* Cbase = C + (size_t)bz * sC + (size_t)(mtile * BlkM) * HW + ntile * BlkN;
#pragma unroll
    for (int f = 0; f < 4; f++) {
#pragma unroll
        for (int nf = 0; nf < 4; nf++) {
            int row = wm + f * 16 + g;
            int col = wn + nf * 8 + t * 2;
            store2(Cbase + (size_t)row * HW + col, acc[f][nf][0], acc[f][nf][1]);
            store2(Cbase + (size_t)(row + 8) * HW + col, acc[f][nf][2], acc[f][nf][3]);
        }
    }
}

// ---------------------------------------------------------------------------
// 4) softmax + lambda: cp.async double-buffered staging of BOTH v and k.
//    grid (bh=128, pair=8), block 128 (4 warps), 2 k-rows per block.
// ---------------------------------------------------------------------------
__global__ __launch_bounds__(128) void k_softmax_lambda(const __half* __restrict__ qkv,
                                                        float* __restrict__ lambda) {
    const int bh = blockIdx.x;
    const int pair = blockIdx.y;
    const int i0 = pair * 2;
    const int b = bh >> 3, nh = bh & 7;
    const __half* kbase = qkv + ((size_t)b * 384 + 128 + nh * 16) * HW;
    const __half* vbase = qkv + ((size_t)b * 384 + 256 + nh * 16) * HW;
    const int tid = threadIdx.x;
    const int warp = tid >> 5, lane = tid & 31;

    __shared__ __half2 vsm[2][16][256];   // 2 x 16 KB
    __shared__ __half2 ksm[2][2][256];    // 2 x 2 KB (2 rows x 512 halves)
    __shared__ float red[4][2][17];

    const uint32_t vsm_base = (uint32_t)__cvta_generic_to_shared(&vsm[0][0][0]);
    const uint32_t ksm_base = (uint32_t)__cvta_generic_to_shared(&ksm[0][0][0]);

    const __half* k0 = kbase + (size_t)(i0 + 0) * HW;
    const __half* k1 = kbase + (size_t)(i0 + 1) * HW;

    // prefetch chunk: v = 1024 cp16 (8/thread), k = 128 cp16 (1/thread)
    auto prefetch = [&](int n0, int buf) {
#pragma unroll
        for (int i = 0; i < 8; i++) {
            int t2 = tid + i * 128;
            int o = t2 >> 6, grp = t2 & 63;
            cp16(vsm_base + (uint32_t)(buf * 16384 + o * 1024 + grp * 16),
                 vbase + (size_t)o * HW + n0 + grp * 8);
        }
        {
            int r = tid >> 6, grp = tid & 63;   // row 0/1, 16B group
            const __half* kr = (r == 0) ? k0 : k1;
            cp16(ksm_base + (uint32_t)(buf * 2048 + r * 1024 + grp * 16),
                 kr + n0 + grp * 8);
        }
        cp_commit();
    };

    float acc0[16], acc1[16];
#pragma unroll
    for (int o = 0; o < 16; o++) { acc0[o] = 0.f; acc1[o] = 0.f; }
    float se0 = 0.f, se1 = 0.f;

    prefetch(0, 0);
    for (int c = 0; c < 8; c++) {
        cp_wait<0>();
        __syncthreads();             // chunk c ready; compute(c-1) fully done
        if (c + 1 < 8) prefetch((c + 1) * 512, (c + 1) & 1);
        const int buf = c & 1;
#pragma unroll
        for (int it = 0; it < 2; it++) {
            int n2 = warp * 64 + it * 32 + lane;
            __half2 kk0 = ksm[buf][0][n2];
            __half2 kk1 = ksm[buf][1][n2];
            float e00 = __expf(__low2float(kk0)), e01 = __expf(__high2float(kk0));
            float e10 = __expf(__low2float(kk1)), e11 = __expf(__high2float(kk1));
            se0 += e00 + e01;
            se1 += e10 + e11;
#pragma unroll
            for (int o = 0; o < 16; o++) {
                __half2 hv = vsm[buf][o][n2];
                float vx = __low2float(hv), vy = __high2float(hv);
                acc0[o] += e00 * vx + e01 * vy;
                acc1[o] += e10 * vx + e11 * vy;
            }
        }
    }

    // warp-level reduction
#pragma unroll
    for (int off = 16; off > 0; off >>= 1) {
        se0 += __shfl_xor_sync(0xffffffff, se0, off);
        se1 += __shfl_xor_sync(0xffffffff, se1, off);
#pragma unroll
        for (int o = 0; o < 16; o++) {
            acc0[o] += __shfl_xor_sync(0xffffffff, acc0[o], off);
            acc1[o] += __shfl_xor_sync(0xffffffff, acc1[o], off);
        }
    }
    if (lane < 16) {
        red[warp][0][lane] = acc0[lane];
        red[warp][1][lane] = acc1[lane];
    } else if (lane == 16) {
        red[warp][0][16] = se0;
        red[warp][1][16] = se1;
    }
    __syncthreads();
    if (tid < 32) {
        int r = tid >> 4, o = tid & 15;
        float a = red[0][r][o] + red[1][r][o] + red[2][r][o] + red[3][r][o];
        float s = red[0][r][16] + red[1][r][16] + red[2][r][16] + red[3][r][16];
        lambda[(size_t)bh * 256 + (i0 + r) * 16 + o] = 0.25f * a / s;
    }
}

// ---------------------------------------------------------------------------
// 5) result1 = content + q * position_lambda (vectorized q load)
// ---------------------------------------------------------------------------
__global__ __launch_bounds__(256) void k_result1(const __half* __restrict__ qkv,
                                                 const float* __restrict__ lambda,
                                                 const float* __restrict__ rel_pos,
                                                 __half* __restrict__ r1) {
    const int bh = blockIdx.z;
    const int b = bh >> 3, nh = bh & 7;
    const int x0 = blockIdx.x * 16, y0 = blockIdx.y * 16;
    const int tid = threadIdx.x;
    const int px = tid & 15, py = tid >> 4;

    __shared__ float lam[16][16];
    __shared__ float relw[16][25];
    __shared__ float qs[16][16][16];
    __shared__ float vs[16][20][20];

    lam[py][px] = lambda[((size_t)bh * 16 + py) * 16 + px];
    for (int t = tid; t < 400; t += 256) relw[t / 25][t % 25] = rel_pos[t];

    // q tile: thread (ch=tid>>4, row=tid&15) loads one 16-half row via 2x uint4
    const __half* qbase = qkv + ((size_t)b * 384 + nh * 16) * HW;
    {
        int ch = tid >> 4, row = tid & 15;
        const uint4* qp = reinterpret_cast<const uint4*>(
            qbase + (size_t)ch * HW + (y0 + row) * Ww + x0);
        uint4 qa = qp[0], qb = qp[1];
        const __half2* ha = reinterpret_cast<const __half2*>(&qa);
        const __half2* hb = reinterpret_cast<const __half2*>(&qb);
#pragma unroll
        for (int j = 0; j < 4; j++) {
            qs[ch][row][j * 2 + 0] = __low2float(ha[j]);
            qs[ch][row][j * 2 + 1] = __high2float(ha[j]);
            qs[ch][row][8 + j * 2 + 0] = __low2float(hb[j]);
            qs[ch][row][8 + j * 2 + 1] = __high2float(hb[j]);
        }
    }

    const __half* vbase = qkv + ((size_t)b * 384 + 256 + nh * 16) * HW;
    for (int t = tid; t < 6400; t += 256) {
        int ch = t / 400;
        int r = t % 400;
        int vy = r / 20, vx = r % 20;
        int gy = y0 + vy - 2, gx = x0 + vx - 2;
        float val = 0.f;
        if (gy >= 0 && gy < Hh && gx >= 0 && gx < Ww)
            val = __half2float(vbase[(size_t)ch * HW + gy * Ww + gx]);
        vs[ch][vy][vx] = val;
    }
    __syncthreads();

    __half* obase = r1 + ((size_t)b * Cc + nh * 16) * HW + (y0 + py) * Ww + x0 + px;
#pragma unroll
    for (int o = 0; o < 16; o++) {
        float content = 0.f;
#pragma unroll
        for (int i = 0; i < 16; i++) content += qs[i][py][px] * lam[i][o];
        float pos = 0.f;
#pragma unroll
        for (int ky = 0; ky < 5; ky++)
#pragma unroll
            for (int kx = 0; kx < 5; kx++)
                pos += relw[o][ky * 5 + kx] * vs[o][py + ky][px + kx];
        obase[(size_t)o * HW] = __float2half_rn(content + qs[o][py][px] * pos);
    }
}

// ---------------------------------------------------------------------------
// Launch
// ---------------------------------------------------------------------------
extern "C" void kernel_launch(void* const* d_in, const int* in_sizes, int n_in,
                              void* d_out, int out_size) {
    const float* src      = (const float*)d_in[0];
    const float* cpe_w    = (const float*)d_in[1];
    const float* qkv_w    = (const float*)d_in[2];
    const float* rel_pos  = (const float*)d_in[3];
    const float* conv1d_w = (const float*)d_in[4];
    const float* out_w    = (const float*)d_in[5];
    float* out = (float*)d_out;

    __half *s_p, *srch_p, *qkv_p, *w2b_p, *r1_p, *wq_p, *w1_p;
    float *lam_p, *pp_p;
    cudaGetSymbolAddress((void**)&s_p,    g_s);
    cudaGetSymbolAddress((void**)&srch_p, g_srch);
    cudaGetSymbolAddress((void**)&qkv_p,  g_qkv);
    cudaGetSymbolAddress((void**)&lam_p,  g_lambda);
    cudaGetSymbolAddress((void**)&pp_p,   g_poolpart);
    cudaGetSymbolAddress((void**)&w2b_p,  g_w2b);
    cudaGetSymbolAddress((void**)&r1_p,   g_r1);
    cudaGetSymbolAddress((void**)&wq_p,   g_wq);
    cudaGetSymbolAddress((void**)&w1_p,   g_w1);

    const int gemm_smem = 3 * (128 * 24 + 16 * 136) * 2;  // 31488 bytes
    cudaFuncSetAttribute(k_mma_gemm<1, __half>, cudaFuncAttributeMaxDynamicSharedMemorySize, gemm_smem);
    cudaFuncSetAttribute(k_mma_gemm<2, float>,  cudaFuncAttributeMaxDynamicSharedMemorySize, gemm_smem);

    k_cpe<<<Bb * Cc * HW / 1024, 256>>>(src, cpe_w, s_p, srch_p, pp_p);
    k_w2b<<<(Bb * OUTC * Cc + 255) / 256, 256>>>(qkv_w, out_w, pp_p, conv1d_w,
                                                 wq_p, w1_p, w2b_p);
    {
        dim3 grid(3 * Cc / 128, HW / 128, Bb);
        k_mma_gemm<1, __half><<<grid, 256, gemm_smem>>>(wq_p, 0,
                                                        s_p, (size_t)Cc * HW,
                                                        nullptr, 0, nullptr, 0,
                                                        qkv_p, (size_t)3 * Cc * HW);
    }
    {
        dim3 grid(Bb * NHh, 8);
        k_softmax_lambda<<<grid, 128>>>(qkv_p, lam_p);
    }
    {
        dim3 grid(Ww / 16, Hh / 16, Bb * NHh);
        k_result1<<<grid, 256>>>(qkv_p, lam_p, rel_pos, r1_p);
    }
    {
        dim3 grid(OUTC / 128, HW / 128, Bb);
        k_mma_gemm<2, float><<<grid, 256, gemm_smem>>>(w1_p, 0,
                                                       r1_p, (size_t)Cc * HW,
                                                       w2b_p, (size_t)OUTC * Cc,
                                                       srch_p, (size_t)Cc * HW,
                                                       out, (size_t)OUTC * HW);
    }
}